// round 16
// baseline (speedup 1.0000x reference)
#include <cuda_runtime.h>
#include <cuda_fp16.h>
#include <cstdint>

#define NN 100000
#define EE 400000
#define NTILES (EE / 64)
#define NT32   (EE / 32)

// ---------------- scratch (static device arrays; no cudaMalloc) ----------------
__device__ __half   g_msgA[(size_t)EE * 128];        // 102.4 MB (fp16 messages)
__device__ __half   g_msgB[(size_t)EE * 128];        // 102.4 MB
__device__ uint32_t g_gi[(size_t)NTILES * 12288];    // 307.2 MB (fp16 gi, fragment order)
__device__ __half   g_amsg[(size_t)NN * 128];        // 25.6 MB  (intermediate agg, fp16)
__device__ float    g_amsgf[(size_t)NN * 128];       // 51.2 MB  (final agg, fp32)

// ---------------- helpers ----------------
__device__ __forceinline__ uint32_t f2t(float x) {
    uint32_t r;
    asm("cvt.rna.tf32.f32 %0, %1;" : "=r"(r) : "f"(x));
    return r;
}
__device__ __forceinline__ uint32_t h2b(float x, float y) {
    __half2 h = __floats2half2_rn(x, y);
    return *(uint32_t*)&h;
}
__device__ __forceinline__ uint32_t hsub2b(uint32_t a, uint32_t b) {
    __half2 r = __hsub2(*(__half2*)&a, *(__half2*)&b);
    return *(uint32_t*)&r;
}

__device__ __forceinline__ void mma8(float* d, const uint32_t* a, const uint32_t* b) {
    asm volatile(
        "mma.sync.aligned.m16n8k8.row.col.f32.tf32.tf32.f32 "
        "{%0,%1,%2,%3}, {%4,%5,%6,%7}, {%8,%9}, {%0,%1,%2,%3};"
        : "+f"(d[0]), "+f"(d[1]), "+f"(d[2]), "+f"(d[3])
        : "r"(a[0]), "r"(a[1]), "r"(a[2]), "r"(a[3]), "r"(b[0]), "r"(b[1]));
}
__device__ __forceinline__ void mma16(float* d, const uint32_t* a, const uint32_t* b) {
    asm volatile(
        "mma.sync.aligned.m16n8k16.row.col.f32.f16.f16.f32 "
        "{%0,%1,%2,%3}, {%4,%5,%6,%7}, {%8,%9}, {%0,%1,%2,%3};"
        : "+f"(d[0]), "+f"(d[1]), "+f"(d[2]), "+f"(d[3])
        : "r"(a[0]), "r"(a[1]), "r"(a[2]), "r"(a[3]), "r"(b[0]), "r"(b[1]));
}
__device__ __forceinline__ void ldsm_x4(uint32_t* r, uint32_t addr) {
    asm volatile("ldmatrix.sync.aligned.m8n8.x4.shared.b16 {%0,%1,%2,%3}, [%4];"
        : "=r"(r[0]), "=r"(r[1]), "=r"(r[2]), "=r"(r[3]) : "r"(addr));
}
__device__ __forceinline__ void cp_async16(uint32_t saddr, const void* gptr) {
    asm volatile("cp.async.cg.shared.global [%0], [%1], 16;" :: "r"(saddr), "l"(gptr));
}
#define CP_COMMIT() asm volatile("cp.async.commit_group;")
#define CP_WAIT1()  asm volatile("cp.async.wait_group 1;" ::: "memory")

// packed f32x2 FMA (PTX-only; ptxas never auto-fuses — SASS_QUICKREF)
__device__ __forceinline__ void fma2(uint64_t& acc, uint64_t a, uint64_t b) {
    asm("fma.rn.f32x2 %0, %1, %2, %0;" : "+l"(acc) : "l"(a), "l"(b));
}
__device__ __forceinline__ float sum2(uint64_t v) {
    float lo, hi;
    asm("mov.b64 {%0,%1}, %2;" : "=f"(lo), "=f"(hi) : "l"(v));
    return lo + hi;
}

__device__ __forceinline__ float fast_tanh(float x) {
    float r;
    asm("tanh.approx.f32 %0, %1;" : "=f"(r) : "f"(x));
    return r;
}
__device__ __forceinline__ float sigm(float x) {
    return 0.5f * fast_tanh(0.5f * x) + 0.5f;
}

// W smem swizzle over p-rows
__device__ __forceinline__ int xsw(int p) {
    return ((p >> 2) & 3) ^ ((((p & 3) ^ (p >> 4)) & 3) << 2);
}

// fp16 layouts (uint32 = half2 words)
#define A2_STRIDE 68                        // 64 half2 words + 4 pad (ldmatrix-safe)
#define A64_WORDS (64 * A2_STRIDE)          // 4352 (k_init 64-row tile)
#define A32_WORDS (32 * A2_STRIDE)          // 2176 (k_step 32-row tile)
#define W2_WORDS  (32 * 768)                // 24576
#define G32_WORDS 6144                      // gi per 32-row tile (256 thr x 24)
#define GRP_WORDS (2 * A32_WORDS + 2 * G32_WORDS)   // 16640 per group (k_step)
#define WET_WORDS 4352                      // W_edge^T paired: 128 cols x 17 float2
#define SMEM_STEP ((W2_WORDS + 2 * GRP_WORDS) * 4)               // 231424 B
#define SMEM_INIT ((A64_WORDS + W2_WORDS + WET_WORDS + 2048 + 2048) * 4)  // 149504 B
#define RO_A_STRIDE 260
#define RO_W_STRIDE 520
#define SMEM_RO ((64 * RO_A_STRIDE + 16 * RO_W_STRIDE) * 4)      // 99840 B

// group-scoped barrier (named barrier grp+1, 256 threads)
#define GBAR(grp) asm volatile("bar.sync %0, %1;" :: "r"((grp) + 1), "r"(256) : "memory")

// no-op kernel: shifts launch index so ncu (-s 5 -c 1) profiles k_step
__global__ void k_nop() {}

// Load entire W [384 x 128] fp32 -> fp16-pair swizzled smem. 512 threads.
__device__ __forceinline__ void load_w_full16(uint32_t* sh_w, const float* __restrict__ W,
                                              int tid) {
#pragma unroll
    for (int it = 0; it < 6; it++) {
        int i = tid + it * 512;             // 0..3071 : (j, ks)
        int j = i >> 3, ks = i & 7;
        const float4* src = (const float4*)(W + (size_t)j * 128 + ks * 16);
        float4 f0 = src[0], f1 = src[1], f2 = src[2], f3 = src[3];
        int pb = ks * 4;
        uint2 v;
        v.x = h2b(f0.x, f0.y); v.y = h2b(f2.x, f2.y);
        *(uint2*)(sh_w + (pb + 0) * 768 + 2 * (j ^ xsw(pb + 0))) = v;
        v.x = h2b(f0.z, f0.w); v.y = h2b(f2.z, f2.w);
        *(uint2*)(sh_w + (pb + 1) * 768 + 2 * (j ^ xsw(pb + 1))) = v;
        v.x = h2b(f1.x, f1.y); v.y = h2b(f3.x, f3.y);
        *(uint2*)(sh_w + (pb + 2) * 768 + 2 * (j ^ xsw(pb + 2))) = v;
        v.x = h2b(f1.z, f1.w); v.y = h2b(f3.z, f3.w);
        *(uint2*)(sh_w + (pb + 3) * 768 + 2 * (j ^ xsw(pb + 3))) = v;
    }
}

// per-lane ldmatrix base offset (bytes): 64-row (k_init, wm in {0,1})
__device__ __forceinline__ uint32_t ldsm_laneoff(int wm, int lane) {
    int rowL = wm * 32 + (lane & 7) + ((lane >> 3) & 1) * 8;
    int koffw = (lane >> 4) * 4;
    return (uint32_t)(rowL * A2_STRIDE + koffw) * 4;
}
// 32-row variant (k_step groups)
__device__ __forceinline__ uint32_t ldsm_laneoff32(int lane) {
    int rowL = (lane & 7) + ((lane >> 3) & 1) * 8;
    int koffw = (lane >> 4) * 4;
    return (uint32_t)(rowL * A2_STRIDE + koffw) * 4;
}

// 64-row GEMM mainloop (k_init): 16 warps, acc[mt][gate*2+q][4]
#define GEMM_MAINLOOP16L(acc, a_u32, sh_w, wn, g, t)                     \
    _Pragma("unroll")                                                    \
    for (int ks = 0; ks < 8; ks++) {                                     \
        uint32_t afr[2][4];                                              \
        ldsm_x4(afr[0], (a_u32) + ks * 32);                              \
        ldsm_x4(afr[1], (a_u32) + 16 * A2_STRIDE * 4 + ks * 32);         \
        int p = ks * 4 + (t);                                            \
        int xs = xsw(p);                                                 \
        const uint32_t* wb = (sh_w) + p * 768;                           \
        _Pragma("unroll")                                                \
        for (int nt = 0; nt < 6; nt++) {                                 \
            int colb = (nt >> 1) * 128 + (wn) * 16 + (nt & 1) * 8;       \
            uint2 b2 = *(const uint2*)(wb + 2 * ((colb + (g)) ^ xs));    \
            mma16(acc[0][nt], afr[0], (const uint32_t*)&b2);             \
            mma16(acc[1][nt], afr[1], (const uint32_t*)&b2);             \
        }                                                                \
    }

// ======================================================================
// k_init (persistent, R13 form: 64-row tiles, f32x2 micro-GEMM):
//   msg0 = fp16(f_edges @ W_edge), row 0 zeroed;
//   gi = fp16(msg0_tile @ W_ih^T + b_ih), FRAGMENT ORDER:
//   gi[tile*12288 + tid*24 + (mt*2+i)*6 + gate*2 + q]
// ======================================================================
__global__ __launch_bounds__(512, 1) void k_init(
    const float* __restrict__ f_edges, const float* __restrict__ W_edge,
    const float* __restrict__ W_ih, const float* __restrict__ b_ih,
    __half* __restrict__ msg0, uint32_t* __restrict__ gi)
{
    extern __shared__ uint32_t smem_u[];
    uint32_t* sh_a16 = smem_u;                                  // 4352 words
    uint32_t* sh_w   = smem_u + A64_WORDS;                      // 24576 words
    float2* sh_wet   = (float2*)(smem_u + A64_WORDS + W2_WORDS); // 128 x 17 float2
    float* sh_fe0 = (float*)(smem_u + A64_WORDS + W2_WORDS + WET_WORDS);
    float* sh_fe1 = sh_fe0 + 2048;

    const int tid = threadIdx.x;
    const int warp = tid >> 5, lane = tid & 31;
    const int wm = warp >> 3, wn = warp & 7;
    const int g = lane >> 2, t = lane & 3;

    const uint32_t fe0s = (uint32_t)__cvta_generic_to_shared(sh_fe0) + tid * 16;
    const uint32_t fe1s = (uint32_t)__cvta_generic_to_shared(sh_fe1) + tid * 16;

    const int tile0 = blockIdx.x;
    cp_async16(fe0s, f_edges + (size_t)tile0 * 64 * 32 + tid * 4);
    CP_COMMIT();

    load_w_full16(sh_w, W_ih, tid);
    // stage W_edge^T paired-k: sh_wet[c*17 + p] = {W_edge[2p][c], W_edge[2p+1][c]}
    for (int i = tid; i < 2048; i += 512) {
        int c = i >> 4, p = i & 15;
        float2 v;
        v.x = __ldg(W_edge + (size_t)(2 * p) * 128 + c);
        v.y = __ldg(W_edge + (size_t)(2 * p + 1) * 128 + c);
        sh_wet[c * 17 + p] = v;
    }

    const uint32_t a_u32 = (uint32_t)__cvta_generic_to_shared(sh_a16) + ldsm_laneoff(wm, lane);

    float2 bi[3][2];
#pragma unroll
    for (int gate = 0; gate < 3; gate++)
#pragma unroll
        for (int q = 0; q < 2; q++)
            bi[gate][q] = *(const float2*)(b_ih + gate * 128 + wn * 16 + q * 8 + 2 * t);

    const int cset[4] = {2 * lane, 2 * lane + 1, 2 * lane + 64, 2 * lane + 65};

    int bufsel = 0;
    for (int tile = tile0; tile < NTILES; tile += gridDim.x) {
        const int e0 = tile * 64;
        int ntile = tile + gridDim.x;
        if (ntile > NTILES - 1) ntile = NTILES - 1;

        const float* fecur = bufsel ? sh_fe1 : sh_fe0;
        uint32_t fens      = bufsel ? fe0s : fe1s;
        bufsel ^= 1;

        cp_async16(fens, f_edges + (size_t)ntile * 64 * 32 + tid * 4);
        CP_COMMIT();
        CP_WAIT1();
        __syncthreads();

        uint64_t acc2[4][4];
#pragma unroll
        for (int r = 0; r < 4; r++)
#pragma unroll
            for (int j = 0; j < 4; j++) acc2[r][j] = 0ull;
#pragma unroll
        for (int p = 0; p < 16; p++) {
            uint64_t wp[4];
#pragma unroll
            for (int j = 0; j < 4; j++)
                wp[j] = *(const uint64_t*)(sh_wet + cset[j] * 17 + p);
#pragma unroll
            for (int r = 0; r < 4; r++) {
                uint64_t fp = *(const uint64_t*)(fecur + (warp + 16 * r) * 32 + 2 * p);
#pragma unroll
                for (int j = 0; j < 4; j++) fma2(acc2[r][j], fp, wp[j]);
            }
        }
#pragma unroll
        for (int r = 0; r < 4; r++) {
            int row = warp + 16 * r;
            int e = e0 + row;
            float v0 = sum2(acc2[r][0]), v1 = sum2(acc2[r][1]);
            float v2 = sum2(acc2[r][2]), v3 = sum2(acc2[r][3]);
            if (e == 0) { v0 = v1 = v2 = v3 = 0.f; }
            uint32_t p0 = h2b(v0, v1), p1 = h2b(v2, v3);
            sh_a16[row * A2_STRIDE + lane]      = p0;
            sh_a16[row * A2_STRIDE + 32 + lane] = p1;
            *(uint32_t*)(msg0 + (size_t)e * 128 + 2 * lane)      = p0;
            *(uint32_t*)(msg0 + (size_t)e * 128 + 64 + 2 * lane) = p1;
        }
        __syncthreads();

        float acc[2][6][4];
#pragma unroll
        for (int a = 0; a < 2; a++)
#pragma unroll
            for (int b = 0; b < 6; b++)
#pragma unroll
                for (int c = 0; c < 4; c++) acc[a][b][c] = 0.f;

        GEMM_MAINLOOP16L(acc, a_u32, sh_w, wn, g, t)

        uint32_t ow[24];
#pragma unroll
        for (int mt = 0; mt < 2; mt++)
#pragma unroll
            for (int i = 0; i < 2; i++)
#pragma unroll
                for (int gate = 0; gate < 3; gate++)
#pragma unroll
                    for (int q = 0; q < 2; q++) {
                        float ox = acc[mt][gate * 2 + q][2 * i]     + bi[gate][q].x;
                        float oy = acc[mt][gate * 2 + q][2 * i + 1] + bi[gate][q].y;
                        ow[(mt * 2 + i) * 6 + gate * 2 + q] = h2b(ox, oy);
                    }
        uint32_t* gdst = gi + (size_t)tile * 12288 + tid * 24;
#pragma unroll
        for (int kk = 0; kk < 6; kk++)
            *(uint4*)(gdst + kk * 4) = ((uint4*)ow)[kk];
    }
}

// ======================================================================
// k_agg (fp16 out) / k_agg_f (fp32 out, final)
// ======================================================================
__global__ __launch_bounds__(256) void k_agg(
    const __half* __restrict__ msg, const int* __restrict__ n2e,
    __half* __restrict__ amsg)
{
    int gid = blockIdx.x * 256 + threadIdx.x;
    int node = gid >> 5, lane = gid & 31;
    const int* ne = n2e + node * 6;
    float4 acc = {0.f, 0.f, 0.f, 0.f};
#pragma unroll
    for (int k = 0; k < 6; k++) {
        int e = __ldg(ne + k);
        uint2 v = ((const uint2*)(msg + (size_t)e * 128))[lane];
        float2 f0 = __half22float2(*(__half2*)&v.x);
        float2 f1 = __half22float2(*(__half2*)&v.y);
        acc.x += f0.x; acc.y += f0.y; acc.z += f1.x; acc.w += f1.y;
    }
    uint2 o;
    o.x = h2b(acc.x, acc.y);
    o.y = h2b(acc.z, acc.w);
    ((uint2*)(amsg + (size_t)node * 128))[lane] = o;
}

__global__ __launch_bounds__(256) void k_agg_f(
    const __half* __restrict__ msg, const int* __restrict__ n2e,
    float* __restrict__ amsgf)
{
    int gid = blockIdx.x * 256 + threadIdx.x;
    int node = gid >> 5, lane = gid & 31;
    const int* ne = n2e + node * 6;
    float4 acc = {0.f, 0.f, 0.f, 0.f};
#pragma unroll
    for (int k = 0; k < 6; k++) {
        int e = __ldg(ne + k);
        uint2 v = ((const uint2*)(msg + (size_t)e * 128))[lane];
        float2 f0 = __half22float2(*(__half2*)&v.x);
        float2 f1 = __half22float2(*(__half2*)&v.y);
        acc.x += f0.x; acc.y += f0.y; acc.z += f1.x; acc.w += f1.y;
    }
    ((float4*)(amsgf + (size_t)node * 128))[lane] = acc;
}

// issue gather LDGs into registers (row within a 32-row tile)
__device__ __forceinline__ void gather_ldg32(
    uint4* rva, uint4* rvb, const __half* __restrict__ amsg,
    const __half* __restrict__ msg_in,
    const int* __restrict__ edge2node, const int* __restrict__ b2revb,
    int T, int row, int part)
{
    int e = T * 32 + row;
    int sn = __ldg(edge2node + e);
    int sr = __ldg(b2revb + e);
    const uint4* pa = (const uint4*)(amsg + (size_t)sn * 128) + part * 2;
    const uint4* pb = (const uint4*)(msg_in + (size_t)sr * 128) + part * 2;
    rva[0] = pa[0]; rva[1] = pa[1];
    rvb[0] = pb[0]; rvb[1] = pb[1];
}
__device__ __forceinline__ void gather_sts32(
    uint32_t* dst, const uint4* rva, const uint4* rvb, int row, int part)
{
#pragma unroll
    for (int c = 0; c < 2; c++) {
        uint4 o;
        o.x = hsub2b(rva[c].x, rvb[c].x); o.y = hsub2b(rva[c].y, rvb[c].y);
        o.z = hsub2b(rva[c].z, rvb[c].z); o.w = hsub2b(rva[c].w, rvb[c].w);
        *(uint4*)(dst + row * A2_STRIDE + part * 8 + c * 4) = o;
    }
}

// ======================================================================
// k_step (persistent, warp-group ping-pong + STAGED coalesced stores):
//   GBAR after GEMM ensures all warps' ldmatrix reads of acur complete
//   BEFORE the epilogue overwrites the tile in place (fixes R15 race).
//   Then a second GBAR and each thread copies its (row,part) slice out
//   with 2 perfectly-coalesced STG.128.
// ======================================================================
__global__ __launch_bounds__(512, 1) void k_step(
    const __half* __restrict__ amsg, const __half* __restrict__ msg_in,
    const int* __restrict__ edge2node, const int* __restrict__ b2revb,
    const float* __restrict__ W_hh, const float* __restrict__ b_hh,
    const uint32_t* __restrict__ gi, __half* __restrict__ msg_out)
{
    extern __shared__ uint32_t smem_u[];
    uint32_t* sh_w = smem_u;                                 // 24576 words (shared)
    const int tid = threadIdx.x;
    const int grp = tid >> 8;
    const int gt  = tid & 255;
    uint32_t* base = smem_u + W2_WORDS + grp * GRP_WORDS;
    uint32_t* sh_a0 = base;
    uint32_t* sh_a1 = base + A32_WORDS;
    uint32_t* sh_g0 = base + 2 * A32_WORDS;
    uint32_t* sh_g1 = sh_g0 + G32_WORDS;

    const int lane = tid & 31;
    const int wn = (gt >> 5);
    const int g = lane >> 2, t = lane & 3;
    const int row = gt >> 3, part = gt & 7;

    load_w_full16(sh_w, W_hh, tid);

    const uint32_t lo = ldsm_laneoff32(lane);
    const uint32_t a0_u32 = (uint32_t)__cvta_generic_to_shared(sh_a0) + lo;
    const uint32_t a1_u32 = (uint32_t)__cvta_generic_to_shared(sh_a1) + lo;
    const uint32_t g0s = (uint32_t)__cvta_generic_to_shared(sh_g0) + gt * 96;
    const uint32_t g1s = (uint32_t)__cvta_generic_to_shared(sh_g1) + gt * 96;
    uint32_t* g0p = sh_g0 + gt * 24;
    uint32_t* g1p = sh_g1 + gt * 24;

    float2 bh[3][2];
#pragma unroll
    for (int gate = 0; gate < 3; gate++)
#pragma unroll
        for (int q = 0; q < 2; q++)
            bh[gate][q] = *(const float2*)(b_hh + gate * 128 + wn * 16 + q * 8 + 2 * t);

    const int jcol = wn * 16 + 2 * t;

    __syncthreads();   // W visible to both groups

    const int T0 = 2 * blockIdx.x + grp;
    const int TSTRIDE = 2 * gridDim.x;

    // ---- prologue ----
    {
        const uint32_t* gsrc = gi + (size_t)(T0 >> 1) * 12288 + ((T0 & 1) * 256 + gt) * 24;
#pragma unroll
        for (int kk = 0; kk < 6; kk++)
            cp_async16(g0s + kk * 16, gsrc + kk * 4);
        CP_COMMIT();
        uint4 rva[2], rvb[2];
        gather_ldg32(rva, rvb, amsg, msg_in, edge2node, b2revb, T0, row, part);
        gather_sts32(sh_a0, rva, rvb, row, part);
    }
    GBAR(grp);

    int bufsel = 0;
    for (int T = T0; T < NT32; T += TSTRIDE) {
        int nT = T + TSTRIDE;
        if (nT > NT32 - 1) nT = NT32 - 1;

        uint32_t* gcur    = bufsel ? g1p : g0p;
        uint32_t  gns     = bufsel ? g0s : g1s;
        uint32_t* acur    = bufsel ? sh_a1 : sh_a0;
        uint32_t* anext   = bufsel ? sh_a0 : sh_a1;
        const uint32_t cur_u32 = bufsel ? a1_u32 : a0_u32;
        bufsel ^= 1;

        // 1. prefetch gi(nT)
        {
            const uint32_t* gsrc = gi + (size_t)(nT >> 1) * 12288 + ((nT & 1) * 256 + gt) * 24;
#pragma unroll
            for (int kk = 0; kk < 6; kk++)
                cp_async16(gns + kk * 16, gsrc + kk * 4);
            CP_COMMIT();
        }

        // 2. issue gather LDGs for nT
        uint4 rva[2], rvb[2];
        gather_ldg32(rva, rvb, amsg, msg_in, edge2node, b2revb, nT, row, part);

        // 3. G_cur complete
        CP_WAIT1();

        // 4. init acc: r,z = gi + b_hh ; n = 0
        float acc[2][6][4];
#pragma unroll
        for (int mt = 0; mt < 2; mt++) {
#pragma unroll
            for (int i = 0; i < 2; i++) {
                int gb = (mt * 2 + i) * 6;
                uint2 r2 = *(const uint2*)(gcur + gb);
                uint2 z2 = *(const uint2*)(gcur + gb + 2);
#pragma unroll
                for (int q = 0; q < 2; q++) {
                    float2 vr = __half22float2(*(__half2*)((q == 0) ? &r2.x : &r2.y));
                    acc[mt][q][2 * i]     = vr.x + bh[0][q].x;
                    acc[mt][q][2 * i + 1] = vr.y + bh[0][q].y;
                    float2 vz = __half22float2(*(__half2*)((q == 0) ? &z2.x : &z2.y));
                    acc[mt][2 + q][2 * i]     = vz.x + bh[1][q].x;
                    acc[mt][2 + q][2 * i + 1] = vz.y + bh[1][q].y;
                    acc[mt][4 + q][2 * i] = 0.f;
                    acc[mt][4 + q][2 * i + 1] = 0.f;
                }
            }
        }

        // 5. GEMM (32 rows)
#pragma unroll
        for (int ks = 0; ks < 8; ks++) {
            uint32_t afr[2][4];
            ldsm_x4(afr[0], cur_u32 + ks * 32);
            ldsm_x4(afr[1], cur_u32 + 16 * A2_STRIDE * 4 + ks * 32);
            int p = ks * 4 + t;
            int xs = xsw(p);
            const uint32_t* wb = sh_w + p * 768;
#pragma unroll
            for (int nt = 0; nt < 6; nt++) {
                int colb = (nt >> 1) * 128 + wn * 16 + (nt & 1) * 8;
                uint2 b2 = *(const uint2*)(wb + 2 * ((colb + g) ^ xs));
                mma16(acc[0][nt], afr[0], (const uint32_t*)&b2);
                mma16(acc[1][nt], afr[1], (const uint32_t*)&b2);
            }
        }

        // 5b. all warps' ldmatrix reads of acur are done before overwrite
        GBAR(grp);

        // 6. GRU epilogue — write o back into the A tile (same coords as hh)
#pragma unroll
        for (int mt = 0; mt < 2; mt++) {
#pragma unroll
            for (int i = 0; i < 2; i++) {
                int erow = mt * 16 + i * 8 + g;
                int e = T * 32 + erow;
                int gb = (mt * 2 + i) * 6;
                uint2 n2 = *(const uint2*)(gcur + gb + 4);
#pragma unroll
                for (int q = 0; q < 2; q++) {
                    int j = jcol + q * 8;
                    float r0 = sigm(acc[mt][q][2 * i]);
                    float r1 = sigm(acc[mt][q][2 * i + 1]);
                    float z0 = sigm(acc[mt][2 + q][2 * i]);
                    float z1 = sigm(acc[mt][2 + q][2 * i + 1]);
                    float ghn0 = acc[mt][4 + q][2 * i]     + bh[2][q].x;
                    float ghn1 = acc[mt][4 + q][2 * i + 1] + bh[2][q].y;
                    float2 ginf = __half22float2(*(__half2*)((q == 0) ? &n2.x : &n2.y));
                    float n0 = fast_tanh(ginf.x + r0 * ghn0);
                    float n1 = fast_tanh(ginf.y + r1 * ghn1);
                    float2 hh = __half22float2(*(__half2*)(acur + erow * A2_STRIDE + (j >> 1)));
                    float o0 = (1.f - z0) * n0 + z0 * hh.x;
                    float o1 = (1.f - z1) * n1 + z1 * hh.y;
                    if (e == 0) { o0 = 0.f; o1 = 0.f; }
                    acur[erow * A2_STRIDE + (j >> 1)] = h2b(o0, o1);
                }
            }
        }
        GBAR(grp);   // all o values staged in acur

        // 6b. coalesced copy-out: 2 LDS.128 + 2 STG.128 per thread
        {
            const uint32_t* srcp = acur + row * A2_STRIDE + part * 8;
            __half* dstp = msg_out + (size_t)(T * 32 + row) * 128 + part * 16;
            uint4 v0 = *(const uint4*)(srcp);
            uint4 v1 = *(const uint4*)(srcp + 4);
            *(uint4*)(dstp) = v0;
            *(uint4*)(dstp + 8) = v1;
        }

        // 7. consume gather regs -> A_next; group barrier
        gather_sts32(anext, rva, rvb, row, part);
        GBAR(grp);
    }
}

// ======================================================================
// k_readout: out = relu([emb[f_nodes], amsgf] @ W_ro + b_ro)  (fp32 amsg)
// ======================================================================
__global__ __launch_bounds__(256) void k_readout(
    const int* __restrict__ f_nodes, const float* __restrict__ emb,
    const float* __restrict__ amsgf, const float* __restrict__ W_ro,
    const float* __restrict__ b_ro, float* __restrict__ out)
{
    extern __shared__ float smem[];
    float* sh_a = smem;
    uint32_t* sh_w = (uint32_t*)(smem + 64 * RO_A_STRIDE);

    const int tid = threadIdx.x;
    const int n0 = blockIdx.x * 64;

    {
        int row = tid >> 2, part = tid & 3;
        int n = n0 + row;
        bool valid = n < NN;
        int nc = valid ? n : (NN - 1);
        int tok = __ldg(f_nodes + nc);
        const float4* pe = (const float4*)(emb + (size_t)tok * 128);
        const float4* pm = (const float4*)(amsgf + (size_t)nc * 128);
#pragma unroll
        for (int c = 0; c < 16; c++) {
            int c4 = part * 16 + c;
            float4 v;
            if (!valid) { v.x = v.y = v.z = v.w = 0.f; }
            else if (c4 < 32) v = pe[c4];
            else v = pm[c4 - 32];
            *(float4*)(sh_a + row * RO_A_STRIDE + c4 * 4) = v;
        }
    }

    const int warp = tid >> 5, lane = tid & 31;
    const int wm = warp >> 2, wn = warp & 3;
    const int g = lane >> 2, t = lane & 3;

    float acc[2][8][4];
#pragma unroll
    for (int a = 0; a < 2; a++)
#pragma unroll
        for (int b = 0; b < 8; b++)
#pragma unroll
            for (int c = 0; c < 4; c++) acc[a][b][c] = 0.f;

    for (int kc = 0; kc < 256; kc += 32) {
        __syncthreads();
#pragma unroll
        for (int it = 0; it < 4; it++) {
            int i = tid + it * 256;
            int p = i >> 6, n4 = i & 63;
            int ks = p >> 2, tt = p & 3;
            const float* srcL = W_ro + (size_t)(kc + ks * 8 + tt) * 256 + n4 * 4;
            const float* srcH = W_ro + (size_t)(kc + ks * 8 + tt + 4) * 256 + n4 * 4;
            float4 lof = *(const float4*)srcL;
            float4 hif = *(const float4*)srcH;
            uint32_t* dst = sh_w + p * RO_W_STRIDE + n4 * 8;
            dst[0] = f2t(lof.x); dst[1] = f2t(hif.x);
            dst[2] = f2t(lof.y); dst[3] = f2t(hif.y);
            dst[4] = f2t(lof.z); dst[5] = f2t(hif.z);
            dst[6] = f2t(lof.w); dst[7] = f2t(hif.w);
        }
        __syncthreads();
#pragma unroll
        for (int ks = 0; ks < 4; ks++) {
            uint32_t afr[2][4];
#pragma unroll
            for (int mt = 0; mt < 2; mt++) {
                const float* base = sh_a + (wm * 32 + mt * 16 + g) * RO_A_STRIDE + kc + ks * 8 + t;
                afr[mt][0] = f2t(base[0]);
                afr[mt][1] = f2t(base[8 * RO_A_STRIDE]);
                afr[mt][2] = f2t(base[4]);
                afr[mt][3] = f2t(base[8 * RO_A_STRIDE + 4]);
            }
#pragma unroll
            for (int nt = 0; nt < 8; nt++) {
                int colb = wn * 64 + nt * 8;
                uint2 b2 = *(const uint2*)(sh_w + (ks * 4 + t) * RO_W_STRIDE + (colb + g) * 2);
                mma8(acc[0][nt], afr[0], (const uint32_t*)&b2);
                mma8(acc[1][nt], afr[1], (const uint32_t*)&b2);
            }
        }
    }

#pragma unroll
    for (int mt = 0; mt < 2; mt++) {
#pragma unroll
        for (int i = 0; i < 2; i++) {
            int row = wm * 32 + mt * 16 + i * 8 + g;
            int n = n0 + row;
            if (n >= NN) continue;
#pragma unroll
            for (int nt = 0; nt < 8; nt++) {
                int col = wn * 64 + nt * 8 + 2 * t;
                float2 br = *(const float2*)(b_ro + col);
                float2 o;
                o.x = fmaxf(acc[mt][nt][2 * i] + br.x, 0.f);
                o.y = fmaxf(acc[mt][nt][2 * i + 1] + br.y, 0.f);
                *(float2*)(out + (size_t)n * 256 + col) = o;
            }
        }
    }
}

// ======================================================================
extern "C" void kernel_launch(void* const* d_in, const int* in_sizes, int n_in,
                              void* d_out, int out_size)
{
    const int*   f_nodes   = (const int*)d_in[0];
    const float* f_edges   = (const float*)d_in[1];
    const int*   node2edge = (const int*)d_in[2];
    const int*   edge2node = (const int*)d_in[3];
    const int*   b2revb    = (const int*)d_in[4];
    const float* emb       = (const float*)d_in[5];
    const float* W_edge    = (const float*)d_in[6];
    const float* W_ih      = (const float*)d_in[7];
    const float* W_hh      = (const float*)d_in[8];
    const float* b_ih      = (const float*)d_in[9];
    const float* b_hh      = (const float*)d_in[10];
    const float* W_ro      = (const float*)d_in[11];
    const float* b_ro      = (const float*)d_in[12];
    float* outp = (float*)d_out;

    __half *msgA, *msgB, *amsgP;
    uint32_t* giP;
    float* amsgfP;
    cudaGetSymbolAddress((void**)&msgA, g_msgA);
    cudaGetSymbolAddress((void**)&msgB, g_msgB);
    cudaGetSymbolAddress((void**)&giP, g_gi);
    cudaGetSymbolAddress((void**)&amsgP, g_amsg);
    cudaGetSymbolAddress((void**)&amsgfP, g_amsgf);

    cudaFuncSetAttribute(k_init,    cudaFuncAttributeMaxDynamicSharedMemorySize, SMEM_INIT);
    cudaFuncSetAttribute(k_step,    cudaFuncAttributeMaxDynamicSharedMemorySize, SMEM_STEP);
    cudaFuncSetAttribute(k_readout, cudaFuncAttributeMaxDynamicSharedMemorySize, SMEM_RO);

    const int PGRID = 152;   // persistent: 1 CTA per SM (GB300 = 152 SMs)

    k_init<<<PGRID, 512, SMEM_INIT>>>(f_edges, W_edge, W_ih, b_ih, msgA, giP);
    k_nop<<<1, 32>>>();   // shifts ncu -s 5 capture onto k_step

    __half* cur = msgA;
    __half* nxt = msgB;
    for (int s = 0; s < 4; s++) {
        k_agg<<<(NN * 32) / 256, 256>>>(cur, node2edge, amsgP);
        k_step<<<PGRID, 512, SMEM_STEP>>>(amsgP, cur, edge2node, b2revb,
                                          W_hh, b_hh, giP, nxt);
        __half* tmp = cur; cur = nxt; nxt = tmp;
    }
    k_agg_f<<<(NN * 32) / 256, 256>>>(cur, node2edge, amsgfP);
    k_readout<<<(NN + 63) / 64, 256, SMEM_RO>>>(f_nodes, emb, amsgfP, W_ro, b_ro, outp);
}

// round 17
// speedup vs baseline: 1.1354x; 1.1354x over previous
#include <cuda_runtime.h>
#include <cuda_fp16.h>
#include <cstdint>

#define NN 100000
#define EE 400000
#define NTILES (EE / 64)
#define NT32   (EE / 32)

// ---------------- scratch (static device arrays; no cudaMalloc) ----------------
__device__ __half   g_msgA[(size_t)EE * 128];        // 102.4 MB (fp16 messages)
__device__ __half   g_msgB[(size_t)EE * 128];        // 102.4 MB
__device__ uint32_t g_gi[(size_t)NTILES * 12288];    // 307.2 MB (fp16 gi, fragment order)
__device__ __half   g_amsg[(size_t)NN * 128];        // 25.6 MB  (intermediate agg, fp16)
__device__ float    g_amsgf[(size_t)NN * 128];       // 51.2 MB  (final agg, fp32)

// ---------------- helpers ----------------
__device__ __forceinline__ uint32_t f2t(float x) {
    uint32_t r;
    asm("cvt.rna.tf32.f32 %0, %1;" : "=r"(r) : "f"(x));
    return r;
}
__device__ __forceinline__ uint32_t h2b(float x, float y) {
    __half2 h = __floats2half2_rn(x, y);
    return *(uint32_t*)&h;
}
__device__ __forceinline__ uint32_t hsub2b(uint32_t a, uint32_t b) {
    __half2 r = __hsub2(*(__half2*)&a, *(__half2*)&b);
    return *(uint32_t*)&r;
}

__device__ __forceinline__ void mma8(float* d, const uint32_t* a, const uint32_t* b) {
    asm volatile(
        "mma.sync.aligned.m16n8k8.row.col.f32.tf32.tf32.f32 "
        "{%0,%1,%2,%3}, {%4,%5,%6,%7}, {%8,%9}, {%0,%1,%2,%3};"
        : "+f"(d[0]), "+f"(d[1]), "+f"(d[2]), "+f"(d[3])
        : "r"(a[0]), "r"(a[1]), "r"(a[2]), "r"(a[3]), "r"(b[0]), "r"(b[1]));
}
__device__ __forceinline__ void mma16(float* d, const uint32_t* a, const uint32_t* b) {
    asm volatile(
        "mma.sync.aligned.m16n8k16.row.col.f32.f16.f16.f32 "
        "{%0,%1,%2,%3}, {%4,%5,%6,%7}, {%8,%9}, {%0,%1,%2,%3};"
        : "+f"(d[0]), "+f"(d[1]), "+f"(d[2]), "+f"(d[3])
        : "r"(a[0]), "r"(a[1]), "r"(a[2]), "r"(a[3]), "r"(b[0]), "r"(b[1]));
}
__device__ __forceinline__ void ldsm_x4(uint32_t* r, uint32_t addr) {
    asm volatile("ldmatrix.sync.aligned.m8n8.x4.shared.b16 {%0,%1,%2,%3}, [%4];"
        : "=r"(r[0]), "=r"(r[1]), "=r"(r[2]), "=r"(r[3]) : "r"(addr));
}
__device__ __forceinline__ void cp_async16(uint32_t saddr, const void* gptr) {
    asm volatile("cp.async.cg.shared.global [%0], [%1], 16;" :: "r"(saddr), "l"(gptr));
}
#define CP_COMMIT() asm volatile("cp.async.commit_group;")
#define CP_WAIT1()  asm volatile("cp.async.wait_group 1;" ::: "memory")

// packed f32x2 FMA (PTX-only; ptxas never auto-fuses — SASS_QUICKREF)
__device__ __forceinline__ void fma2(uint64_t& acc, uint64_t a, uint64_t b) {
    asm("fma.rn.f32x2 %0, %1, %2, %0;" : "+l"(acc) : "l"(a), "l"(b));
}
__device__ __forceinline__ float sum2(uint64_t v) {
    float lo, hi;
    asm("mov.b64 {%0,%1}, %2;" : "=f"(lo), "=f"(hi) : "l"(v));
    return lo + hi;
}

__device__ __forceinline__ float fast_tanh(float x) {
    float r;
    asm("tanh.approx.f32 %0, %1;" : "=f"(r) : "f"(x));
    return r;
}
__device__ __forceinline__ float sigm(float x) {
    return 0.5f * fast_tanh(0.5f * x) + 0.5f;
}

// W smem swizzle over p-rows
__device__ __forceinline__ int xsw(int p) {
    return ((p >> 2) & 3) ^ ((((p & 3) ^ (p >> 4)) & 3) << 2);
}

// fp16 layouts (uint32 = half2 words)
#define A2_STRIDE 68                        // 64 half2 words + 4 pad (ldmatrix-safe)
#define A64_WORDS (64 * A2_STRIDE)          // 4352 (k_init 64-row tile)
#define A32_WORDS (32 * A2_STRIDE)          // 2176 (k_step 32-row tile)
#define W2_WORDS  (32 * 768)                // 24576
#define G32_WORDS 6144                      // gi per 32-row tile (256 thr x 24)
#define GRP_WORDS (2 * A32_WORDS + 2 * G32_WORDS)   // 16640 per group (k_step)
#define WET_WORDS 4352                      // W_edge^T paired: 128 cols x 17 float2
#define SMEM_STEP ((W2_WORDS + 2 * GRP_WORDS) * 4)               // 231424 B
#define SMEM_INIT ((A64_WORDS + W2_WORDS + WET_WORDS + 2048 + 2048) * 4)  // 149504 B
#define RO_A_STRIDE 260
#define RO_W_STRIDE 520
#define SMEM_RO ((64 * RO_A_STRIDE + 16 * RO_W_STRIDE) * 4)      // 99840 B

// group-scoped barrier (named barrier grp+1, 256 threads)
#define GBAR(grp) asm volatile("bar.sync %0, %1;" :: "r"((grp) + 1), "r"(256) : "memory")

// Load entire W [384 x 128] fp32 -> fp16-pair swizzled smem. 512 threads.
__device__ __forceinline__ void load_w_full16(uint32_t* sh_w, const float* __restrict__ W,
                                              int tid) {
#pragma unroll
    for (int it = 0; it < 6; it++) {
        int i = tid + it * 512;             // 0..3071 : (j, ks)
        int j = i >> 3, ks = i & 7;
        const float4* src = (const float4*)(W + (size_t)j * 128 + ks * 16);
        float4 f0 = src[0], f1 = src[1], f2 = src[2], f3 = src[3];
        int pb = ks * 4;
        uint2 v;
        v.x = h2b(f0.x, f0.y); v.y = h2b(f2.x, f2.y);
        *(uint2*)(sh_w + (pb + 0) * 768 + 2 * (j ^ xsw(pb + 0))) = v;
        v.x = h2b(f0.z, f0.w); v.y = h2b(f2.z, f2.w);
        *(uint2*)(sh_w + (pb + 1) * 768 + 2 * (j ^ xsw(pb + 1))) = v;
        v.x = h2b(f1.x, f1.y); v.y = h2b(f3.x, f3.y);
        *(uint2*)(sh_w + (pb + 2) * 768 + 2 * (j ^ xsw(pb + 2))) = v;
        v.x = h2b(f1.z, f1.w); v.y = h2b(f3.z, f3.w);
        *(uint2*)(sh_w + (pb + 3) * 768 + 2 * (j ^ xsw(pb + 3))) = v;
    }
}

// per-lane ldmatrix base offset (bytes): 64-row (k_init, wm in {0,1})
__device__ __forceinline__ uint32_t ldsm_laneoff(int wm, int lane) {
    int rowL = wm * 32 + (lane & 7) + ((lane >> 3) & 1) * 8;
    int koffw = (lane >> 4) * 4;
    return (uint32_t)(rowL * A2_STRIDE + koffw) * 4;
}
// 32-row variant (k_step groups)
__device__ __forceinline__ uint32_t ldsm_laneoff32(int lane) {
    int rowL = (lane & 7) + ((lane >> 3) & 1) * 8;
    int koffw = (lane >> 4) * 4;
    return (uint32_t)(rowL * A2_STRIDE + koffw) * 4;
}

// 64-row GEMM mainloop (k_init): 16 warps, acc[mt][gate*2+q][4]
#define GEMM_MAINLOOP16L(acc, a_u32, sh_w, wn, g, t)                     \
    _Pragma("unroll")                                                    \
    for (int ks = 0; ks < 8; ks++) {                                     \
        uint32_t afr[2][4];                                              \
        ldsm_x4(afr[0], (a_u32) + ks * 32);                              \
        ldsm_x4(afr[1], (a_u32) + 16 * A2_STRIDE * 4 + ks * 32);         \
        int p = ks * 4 + (t);                                            \
        int xs = xsw(p);                                                 \
        const uint32_t* wb = (sh_w) + p * 768;                           \
        _Pragma("unroll")                                                \
        for (int nt = 0; nt < 6; nt++) {                                 \
            int colb = (nt >> 1) * 128 + (wn) * 16 + (nt & 1) * 8;       \
            uint2 b2 = *(const uint2*)(wb + 2 * ((colb + (g)) ^ xs));    \
            mma16(acc[0][nt], afr[0], (const uint32_t*)&b2);             \
            mma16(acc[1][nt], afr[1], (const uint32_t*)&b2);             \
        }                                                                \
    }

// ======================================================================
// k_init (persistent, 64-row tiles, f32x2 packed-FMA micro-GEMM):
//   msg0 = fp16(f_edges @ W_edge), row 0 zeroed;
//   gi = fp16(msg0_tile @ W_ih^T + b_ih), FRAGMENT ORDER:
//   gi[tile*12288 + tid*24 + (mt*2+i)*6 + gate*2 + q]
// ======================================================================
__global__ __launch_bounds__(512, 1) void k_init(
    const float* __restrict__ f_edges, const float* __restrict__ W_edge,
    const float* __restrict__ W_ih, const float* __restrict__ b_ih,
    __half* __restrict__ msg0, uint32_t* __restrict__ gi)
{
    extern __shared__ uint32_t smem_u[];
    uint32_t* sh_a16 = smem_u;                                  // 4352 words
    uint32_t* sh_w   = smem_u + A64_WORDS;                      // 24576 words
    float2* sh_wet   = (float2*)(smem_u + A64_WORDS + W2_WORDS); // 128 x 17 float2
    float* sh_fe0 = (float*)(smem_u + A64_WORDS + W2_WORDS + WET_WORDS);
    float* sh_fe1 = sh_fe0 + 2048;

    const int tid = threadIdx.x;
    const int warp = tid >> 5, lane = tid & 31;
    const int wm = warp >> 3, wn = warp & 7;
    const int g = lane >> 2, t = lane & 3;

    const uint32_t fe0s = (uint32_t)__cvta_generic_to_shared(sh_fe0) + tid * 16;
    const uint32_t fe1s = (uint32_t)__cvta_generic_to_shared(sh_fe1) + tid * 16;

    const int tile0 = blockIdx.x;
    cp_async16(fe0s, f_edges + (size_t)tile0 * 64 * 32 + tid * 4);
    CP_COMMIT();

    load_w_full16(sh_w, W_ih, tid);
    // stage W_edge^T paired-k: sh_wet[c*17 + p] = {W_edge[2p][c], W_edge[2p+1][c]}
    for (int i = tid; i < 2048; i += 512) {
        int c = i >> 4, p = i & 15;
        float2 v;
        v.x = __ldg(W_edge + (size_t)(2 * p) * 128 + c);
        v.y = __ldg(W_edge + (size_t)(2 * p + 1) * 128 + c);
        sh_wet[c * 17 + p] = v;
    }

    const uint32_t a_u32 = (uint32_t)__cvta_generic_to_shared(sh_a16) + ldsm_laneoff(wm, lane);

    float2 bi[3][2];
#pragma unroll
    for (int gate = 0; gate < 3; gate++)
#pragma unroll
        for (int q = 0; q < 2; q++)
            bi[gate][q] = *(const float2*)(b_ih + gate * 128 + wn * 16 + q * 8 + 2 * t);

    const int cset[4] = {2 * lane, 2 * lane + 1, 2 * lane + 64, 2 * lane + 65};

    int bufsel = 0;
    for (int tile = tile0; tile < NTILES; tile += gridDim.x) {
        const int e0 = tile * 64;
        int ntile = tile + gridDim.x;
        if (ntile > NTILES - 1) ntile = NTILES - 1;

        const float* fecur = bufsel ? sh_fe1 : sh_fe0;
        uint32_t fens      = bufsel ? fe0s : fe1s;
        bufsel ^= 1;

        cp_async16(fens, f_edges + (size_t)ntile * 64 * 32 + tid * 4);
        CP_COMMIT();
        CP_WAIT1();
        __syncthreads();

        uint64_t acc2[4][4];
#pragma unroll
        for (int r = 0; r < 4; r++)
#pragma unroll
            for (int j = 0; j < 4; j++) acc2[r][j] = 0ull;
#pragma unroll
        for (int p = 0; p < 16; p++) {
            uint64_t wp[4];
#pragma unroll
            for (int j = 0; j < 4; j++)
                wp[j] = *(const uint64_t*)(sh_wet + cset[j] * 17 + p);
#pragma unroll
            for (int r = 0; r < 4; r++) {
                uint64_t fp = *(const uint64_t*)(fecur + (warp + 16 * r) * 32 + 2 * p);
#pragma unroll
                for (int j = 0; j < 4; j++) fma2(acc2[r][j], fp, wp[j]);
            }
        }
#pragma unroll
        for (int r = 0; r < 4; r++) {
            int row = warp + 16 * r;
            int e = e0 + row;
            float v0 = sum2(acc2[r][0]), v1 = sum2(acc2[r][1]);
            float v2 = sum2(acc2[r][2]), v3 = sum2(acc2[r][3]);
            if (e == 0) { v0 = v1 = v2 = v3 = 0.f; }
            uint32_t p0 = h2b(v0, v1), p1 = h2b(v2, v3);
            sh_a16[row * A2_STRIDE + lane]      = p0;
            sh_a16[row * A2_STRIDE + 32 + lane] = p1;
            *(uint32_t*)(msg0 + (size_t)e * 128 + 2 * lane)      = p0;
            *(uint32_t*)(msg0 + (size_t)e * 128 + 64 + 2 * lane) = p1;
        }
        __syncthreads();

        float acc[2][6][4];
#pragma unroll
        for (int a = 0; a < 2; a++)
#pragma unroll
            for (int b = 0; b < 6; b++)
#pragma unroll
                for (int c = 0; c < 4; c++) acc[a][b][c] = 0.f;

        GEMM_MAINLOOP16L(acc, a_u32, sh_w, wn, g, t)

        uint32_t ow[24];
#pragma unroll
        for (int mt = 0; mt < 2; mt++)
#pragma unroll
            for (int i = 0; i < 2; i++)
#pragma unroll
                for (int gate = 0; gate < 3; gate++)
#pragma unroll
                    for (int q = 0; q < 2; q++) {
                        float ox = acc[mt][gate * 2 + q][2 * i]     + bi[gate][q].x;
                        float oy = acc[mt][gate * 2 + q][2 * i + 1] + bi[gate][q].y;
                        ow[(mt * 2 + i) * 6 + gate * 2 + q] = h2b(ox, oy);
                    }
        uint32_t* gdst = gi + (size_t)tile * 12288 + tid * 24;
#pragma unroll
        for (int kk = 0; kk < 6; kk++)
            *(uint4*)(gdst + kk * 4) = ((uint4*)ow)[kk];
    }
}

// ======================================================================
// k_agg (fp16 out) / k_agg_f (fp32 out, final)
// ======================================================================
__global__ __launch_bounds__(256) void k_agg(
    const __half* __restrict__ msg, const int* __restrict__ n2e,
    __half* __restrict__ amsg)
{
    int gid = blockIdx.x * 256 + threadIdx.x;
    int node = gid >> 5, lane = gid & 31;
    const int* ne = n2e + node * 6;
    float4 acc = {0.f, 0.f, 0.f, 0.f};
#pragma unroll
    for (int k = 0; k < 6; k++) {
        int e = __ldg(ne + k);
        uint2 v = ((const uint2*)(msg + (size_t)e * 128))[lane];
        float2 f0 = __half22float2(*(__half2*)&v.x);
        float2 f1 = __half22float2(*(__half2*)&v.y);
        acc.x += f0.x; acc.y += f0.y; acc.z += f1.x; acc.w += f1.y;
    }
    uint2 o;
    o.x = h2b(acc.x, acc.y);
    o.y = h2b(acc.z, acc.w);
    ((uint2*)(amsg + (size_t)node * 128))[lane] = o;
}

__global__ __launch_bounds__(256) void k_agg_f(
    const __half* __restrict__ msg, const int* __restrict__ n2e,
    float* __restrict__ amsgf)
{
    int gid = blockIdx.x * 256 + threadIdx.x;
    int node = gid >> 5, lane = gid & 31;
    const int* ne = n2e + node * 6;
    float4 acc = {0.f, 0.f, 0.f, 0.f};
#pragma unroll
    for (int k = 0; k < 6; k++) {
        int e = __ldg(ne + k);
        uint2 v = ((const uint2*)(msg + (size_t)e * 128))[lane];
        float2 f0 = __half22float2(*(__half2*)&v.x);
        float2 f1 = __half22float2(*(__half2*)&v.y);
        acc.x += f0.x; acc.y += f0.y; acc.z += f1.x; acc.w += f1.y;
    }
    ((float4*)(amsgf + (size_t)node * 128))[lane] = acc;
}

// issue gather LDGs into registers (row within a 32-row tile)
__device__ __forceinline__ void gather_ldg32(
    uint4* rva, uint4* rvb, const __half* __restrict__ amsg,
    const __half* __restrict__ msg_in,
    const int* __restrict__ edge2node, const int* __restrict__ b2revb,
    int T, int row, int part)
{
    int e = T * 32 + row;
    int sn = __ldg(edge2node + e);
    int sr = __ldg(b2revb + e);
    const uint4* pa = (const uint4*)(amsg + (size_t)sn * 128) + part * 2;
    const uint4* pb = (const uint4*)(msg_in + (size_t)sr * 128) + part * 2;
    rva[0] = pa[0]; rva[1] = pa[1];
    rvb[0] = pb[0]; rvb[1] = pb[1];
}
__device__ __forceinline__ void gather_sts32(
    uint32_t* dst, const uint4* rva, const uint4* rvb, int row, int part)
{
#pragma unroll
    for (int c = 0; c < 2; c++) {
        uint4 o;
        o.x = hsub2b(rva[c].x, rvb[c].x); o.y = hsub2b(rva[c].y, rvb[c].y);
        o.z = hsub2b(rva[c].z, rvb[c].z); o.w = hsub2b(rva[c].w, rvb[c].w);
        *(uint4*)(dst + row * A2_STRIDE + part * 8 + c * 4) = o;
    }
}

// ======================================================================
// k_step (persistent, warp-group ping-pong — R13 form):
//   2 groups x 8 warps; each group on independent 32-row tiles with its own
//   A/gi double buffers + named barrier. Epilogue (MUFU/LSU) of one group
//   overlaps GEMM (tensor) of the other. 1 GBAR per tile.
// ======================================================================
__global__ __launch_bounds__(512, 1) void k_step(
    const __half* __restrict__ amsg, const __half* __restrict__ msg_in,
    const int* __restrict__ edge2node, const int* __restrict__ b2revb,
    const float* __restrict__ W_hh, const float* __restrict__ b_hh,
    const uint32_t* __restrict__ gi, __half* __restrict__ msg_out)
{
    extern __shared__ uint32_t smem_u[];
    uint32_t* sh_w = smem_u;                                 // 24576 words (shared)
    const int tid = threadIdx.x;
    const int grp = tid >> 8;
    const int gt  = tid & 255;
    uint32_t* base = smem_u + W2_WORDS + grp * GRP_WORDS;
    uint32_t* sh_a0 = base;
    uint32_t* sh_a1 = base + A32_WORDS;
    uint32_t* sh_g0 = base + 2 * A32_WORDS;
    uint32_t* sh_g1 = sh_g0 + G32_WORDS;

    const int lane = tid & 31;
    const int wn = (gt >> 5);
    const int g = lane >> 2, t = lane & 3;
    const int row = gt >> 3, part = gt & 7;

    load_w_full16(sh_w, W_hh, tid);

    const uint32_t lo = ldsm_laneoff32(lane);
    const uint32_t a0_u32 = (uint32_t)__cvta_generic_to_shared(sh_a0) + lo;
    const uint32_t a1_u32 = (uint32_t)__cvta_generic_to_shared(sh_a1) + lo;
    const uint32_t g0s = (uint32_t)__cvta_generic_to_shared(sh_g0) + gt * 96;
    const uint32_t g1s = (uint32_t)__cvta_generic_to_shared(sh_g1) + gt * 96;
    uint32_t* g0p = sh_g0 + gt * 24;
    uint32_t* g1p = sh_g1 + gt * 24;

    float2 bh[3][2];
#pragma unroll
    for (int gate = 0; gate < 3; gate++)
#pragma unroll
        for (int q = 0; q < 2; q++)
            bh[gate][q] = *(const float2*)(b_hh + gate * 128 + wn * 16 + q * 8 + 2 * t);

    const int jcol = wn * 16 + 2 * t;

    __syncthreads();   // W visible to both groups

    const int T0 = 2 * blockIdx.x + grp;
    const int TSTRIDE = 2 * gridDim.x;

    // ---- prologue ----
    {
        const uint32_t* gsrc = gi + (size_t)(T0 >> 1) * 12288 + ((T0 & 1) * 256 + gt) * 24;
#pragma unroll
        for (int kk = 0; kk < 6; kk++)
            cp_async16(g0s + kk * 16, gsrc + kk * 4);
        CP_COMMIT();
        uint4 rva[2], rvb[2];
        gather_ldg32(rva, rvb, amsg, msg_in, edge2node, b2revb, T0, row, part);
        gather_sts32(sh_a0, rva, rvb, row, part);
    }
    GBAR(grp);

    int bufsel = 0;
    for (int T = T0; T < NT32; T += TSTRIDE) {
        int nT = T + TSTRIDE;
        if (nT > NT32 - 1) nT = NT32 - 1;

        uint32_t* gcur    = bufsel ? g1p : g0p;
        uint32_t  gns     = bufsel ? g0s : g1s;
        uint32_t* acur    = bufsel ? sh_a1 : sh_a0;
        uint32_t* anext   = bufsel ? sh_a0 : sh_a1;
        const uint32_t cur_u32 = bufsel ? a1_u32 : a0_u32;
        bufsel ^= 1;

        // 1. prefetch gi(nT)
        {
            const uint32_t* gsrc = gi + (size_t)(nT >> 1) * 12288 + ((nT & 1) * 256 + gt) * 24;
#pragma unroll
            for (int kk = 0; kk < 6; kk++)
                cp_async16(gns + kk * 16, gsrc + kk * 4);
            CP_COMMIT();
        }

        // 2. issue gather LDGs for nT
        uint4 rva[2], rvb[2];
        gather_ldg32(rva, rvb, amsg, msg_in, edge2node, b2revb, nT, row, part);

        // 3. G_cur complete
        CP_WAIT1();

        // 4. init acc: r,z = gi + b_hh ; n = 0
        float acc[2][6][4];
#pragma unroll
        for (int mt = 0; mt < 2; mt++) {
#pragma unroll
            for (int i = 0; i < 2; i++) {
                int gb = (mt * 2 + i) * 6;
                uint2 r2 = *(const uint2*)(gcur + gb);
                uint2 z2 = *(const uint2*)(gcur + gb + 2);
#pragma unroll
                for (int q = 0; q < 2; q++) {
                    float2 vr = __half22float2(*(__half2*)((q == 0) ? &r2.x : &r2.y));
                    acc[mt][q][2 * i]     = vr.x + bh[0][q].x;
                    acc[mt][q][2 * i + 1] = vr.y + bh[0][q].y;
                    float2 vz = __half22float2(*(__half2*)((q == 0) ? &z2.x : &z2.y));
                    acc[mt][2 + q][2 * i]     = vz.x + bh[1][q].x;
                    acc[mt][2 + q][2 * i + 1] = vz.y + bh[1][q].y;
                    acc[mt][4 + q][2 * i] = 0.f;
                    acc[mt][4 + q][2 * i + 1] = 0.f;
                }
            }
        }

        // 5. GEMM (32 rows; afr[0]=rows 0-15, afr[1]=rows 16-31)
#pragma unroll
        for (int ks = 0; ks < 8; ks++) {
            uint32_t afr[2][4];
            ldsm_x4(afr[0], cur_u32 + ks * 32);
            ldsm_x4(afr[1], cur_u32 + 16 * A2_STRIDE * 4 + ks * 32);
            int p = ks * 4 + t;
            int xs = xsw(p);
            const uint32_t* wb = sh_w + p * 768;
#pragma unroll
            for (int nt = 0; nt < 6; nt++) {
                int colb = (nt >> 1) * 128 + wn * 16 + (nt & 1) * 8;
                uint2 b2 = *(const uint2*)(wb + 2 * ((colb + g) ^ xs));
                mma16(acc[0][nt], afr[0], (const uint32_t*)&b2);
                mma16(acc[1][nt], afr[1], (const uint32_t*)&b2);
            }
        }

        // 6. GRU epilogue
#pragma unroll
        for (int mt = 0; mt < 2; mt++) {
#pragma unroll
            for (int i = 0; i < 2; i++) {
                int erow = mt * 16 + i * 8 + g;
                int e = T * 32 + erow;
                int gb = (mt * 2 + i) * 6;
                uint2 n2 = *(const uint2*)(gcur + gb + 4);
#pragma unroll
                for (int q = 0; q < 2; q++) {
                    int j = jcol + q * 8;
                    float r0 = sigm(acc[mt][q][2 * i]);
                    float r1 = sigm(acc[mt][q][2 * i + 1]);
                    float z0 = sigm(acc[mt][2 + q][2 * i]);
                    float z1 = sigm(acc[mt][2 + q][2 * i + 1]);
                    float ghn0 = acc[mt][4 + q][2 * i]     + bh[2][q].x;
                    float ghn1 = acc[mt][4 + q][2 * i + 1] + bh[2][q].y;
                    float2 ginf = __half22float2(*(__half2*)((q == 0) ? &n2.x : &n2.y));
                    float n0 = fast_tanh(ginf.x + r0 * ghn0);
                    float n1 = fast_tanh(ginf.y + r1 * ghn1);
                    float2 hh = __half22float2(*(__half2*)(acur + erow * A2_STRIDE + (j >> 1)));
                    float o0 = (1.f - z0) * n0 + z0 * hh.x;
                    float o1 = (1.f - z1) * n1 + z1 * hh.y;
                    if (e == 0) { o0 = 0.f; o1 = 0.f; }
                    *(uint32_t*)(msg_out + (size_t)e * 128 + j) = h2b(o0, o1);
                }
            }
        }

        // 7. consume gather regs -> A_next; group barrier
        gather_sts32(anext, rva, rvb, row, part);
        GBAR(grp);
    }
}

// ======================================================================
// k_readout: out = relu([emb[f_nodes], amsgf] @ W_ro + b_ro)  (fp32 amsg)
// ======================================================================
__global__ __launch_bounds__(256) void k_readout(
    const int* __restrict__ f_nodes, const float* __restrict__ emb,
    const float* __restrict__ amsgf, const float* __restrict__ W_ro,
    const float* __restrict__ b_ro, float* __restrict__ out)
{
    extern __shared__ float smem[];
    float* sh_a = smem;
    uint32_t* sh_w = (uint32_t*)(smem + 64 * RO_A_STRIDE);

    const int tid = threadIdx.x;
    const int n0 = blockIdx.x * 64;

    {
        int row = tid >> 2, part = tid & 3;
        int n = n0 + row;
        bool valid = n < NN;
        int nc = valid ? n : (NN - 1);
        int tok = __ldg(f_nodes + nc);
        const float4* pe = (const float4*)(emb + (size_t)tok * 128);
        const float4* pm = (const float4*)(amsgf + (size_t)nc * 128);
#pragma unroll
        for (int c = 0; c < 16; c++) {
            int c4 = part * 16 + c;
            float4 v;
            if (!valid) { v.x = v.y = v.z = v.w = 0.f; }
            else if (c4 < 32) v = pe[c4];
            else v = pm[c4 - 32];
            *(float4*)(sh_a + row * RO_A_STRIDE + c4 * 4) = v;
        }
    }

    const int warp = tid >> 5, lane = tid & 31;
    const int wm = warp >> 2, wn = warp & 3;
    const int g = lane >> 2, t = lane & 3;

    float acc[2][8][4];
#pragma unroll
    for (int a = 0; a < 2; a++)
#pragma unroll
        for (int b = 0; b < 8; b++)
#pragma unroll
            for (int c = 0; c < 4; c++) acc[a][b][c] = 0.f;

    for (int kc = 0; kc < 256; kc += 32) {
        __syncthreads();
#pragma unroll
        for (int it = 0; it < 4; it++) {
            int i = tid + it * 256;
            int p = i >> 6, n4 = i & 63;
            int ks = p >> 2, tt = p & 3;
            const float* srcL = W_ro + (size_t)(kc + ks * 8 + tt) * 256 + n4 * 4;
            const float* srcH = W_ro + (size_t)(kc + ks * 8 + tt + 4) * 256 + n4 * 4;
            float4 lof = *(const float4*)srcL;
            float4 hif = *(const float4*)srcH;
            uint32_t* dst = sh_w + p * RO_W_STRIDE + n4 * 8;
            dst[0] = f2t(lof.x); dst[1] = f2t(hif.x);
            dst[2] = f2t(lof.y); dst[3] = f2t(hif.y);
            dst[4] = f2t(lof.z); dst[5] = f2t(hif.z);
            dst[6] = f2t(lof.w); dst[7] = f2t(hif.w);
        }
        __syncthreads();
#pragma unroll
        for (int ks = 0; ks < 4; ks++) {
            uint32_t afr[2][4];
#pragma unroll
            for (int mt = 0; mt < 2; mt++) {
                const float* base = sh_a + (wm * 32 + mt * 16 + g) * RO_A_STRIDE + kc + ks * 8 + t;
                afr[mt][0] = f2t(base[0]);
                afr[mt][1] = f2t(base[8 * RO_A_STRIDE]);
                afr[mt][2] = f2t(base[4]);
                afr[mt][3] = f2t(base[8 * RO_A_STRIDE + 4]);
            }
#pragma unroll
            for (int nt = 0; nt < 8; nt++) {
                int colb = wn * 64 + nt * 8;
                uint2 b2 = *(const uint2*)(sh_w + (ks * 4 + t) * RO_W_STRIDE + (colb + g) * 2);
                mma8(acc[0][nt], afr[0], (const uint32_t*)&b2);
                mma8(acc[1][nt], afr[1], (const uint32_t*)&b2);
            }
        }
    }

#pragma unroll
    for (int mt = 0; mt < 2; mt++) {
#pragma unroll
        for (int i = 0; i < 2; i++) {
            int row = wm * 32 + mt * 16 + i * 8 + g;
            int n = n0 + row;
            if (n >= NN) continue;
#pragma unroll
            for (int nt = 0; nt < 8; nt++) {
                int col = wn * 64 + nt * 8 + 2 * t;
                float2 br = *(const float2*)(b_ro + col);
                float2 o;
                o.x = fmaxf(acc[mt][nt][2 * i] + br.x, 0.f);
                o.y = fmaxf(acc[mt][nt][2 * i + 1] + br.y, 0.f);
                *(float2*)(out + (size_t)n * 256 + col) = o;
            }
        }
    }
}

// ======================================================================
extern "C" void kernel_launch(void* const* d_in, const int* in_sizes, int n_in,
                              void* d_out, int out_size)
{
    const int*   f_nodes   = (const int*)d_in[0];
    const float* f_edges   = (const float*)d_in[1];
    const int*   node2edge = (const int*)d_in[2];
    const int*   edge2node = (const int*)d_in[3];
    const int*   b2revb    = (const int*)d_in[4];
    const float* emb       = (const float*)d_in[5];
    const float* W_edge    = (const float*)d_in[6];
    const float* W_ih      = (const float*)d_in[7];
    const float* W_hh      = (const float*)d_in[8];
    const float* b_ih      = (const float*)d_in[9];
    const float* b_hh      = (const float*)d_in[10];
    const float* W_ro      = (const float*)d_in[11];
    const float* b_ro      = (const float*)d_in[12];
    float* outp = (float*)d_out;

    __half *msgA, *msgB, *amsgP;
    uint32_t* giP;
    float* amsgfP;
    cudaGetSymbolAddress((void**)&msgA, g_msgA);
    cudaGetSymbolAddress((void**)&msgB, g_msgB);
    cudaGetSymbolAddress((void**)&giP, g_gi);
    cudaGetSymbolAddress((void**)&amsgP, g_amsg);
    cudaGetSymbolAddress((void**)&amsgfP, g_amsgf);

    cudaFuncSetAttribute(k_init,    cudaFuncAttributeMaxDynamicSharedMemorySize, SMEM_INIT);
    cudaFuncSetAttribute(k_step,    cudaFuncAttributeMaxDynamicSharedMemorySize, SMEM_STEP);
    cudaFuncSetAttribute(k_readout, cudaFuncAttributeMaxDynamicSharedMemorySize, SMEM_RO);

    const int PGRID = 152;   // persistent: 1 CTA per SM (GB300 = 152 SMs)

    k_init<<<PGRID, 512, SMEM_INIT>>>(f_edges, W_edge, W_ih, b_ih, msgA, giP);

    __half* cur = msgA;
    __half* nxt = msgB;
    for (int s = 0; s < 4; s++) {
        k_agg<<<(NN * 32) / 256, 256>>>(cur, node2edge, amsgP);
        k_step<<<PGRID, 512, SMEM_STEP>>>(amsgP, cur, edge2node, b2revb,
                                          W_hh, b_hh, giP, nxt);
        __half* tmp = cur; cur = nxt; nxt = tmp;
    }
    k_agg_f<<<(NN * 32) / 256, 256>>>(cur, node2edge, amsgfP);
    k_readout<<<(NN + 63) / 64, 256, SMEM_RO>>>(f_nodes, emb, amsgfP, W_ro, b_ro, outp);
}